// round 1
// baseline (speedup 1.0000x reference)
#include <cuda_runtime.h>
#include <math.h>

#define NN 50000
#define NE 800000
#define DD 128
#define PX 132   // padded smem row stride (132*4B=528B, 16B aligned; 132%32=4 -> <=2-way conflicts)

// ------------------------- scratch (device globals; no allocs allowed) ----
__device__ float g_q[NN * DD];
__device__ float g_k[NN * DD];
__device__ float g_v[NN * DD];
__device__ float g_den[NN * DD];
__device__ float g_h[NN * DD];
__device__ float g_p[(size_t)NE * DD];

// ---------------------------------------------------------------------------
// Generic linear: Y[M,128] = X[M,128] @ W[128,128] + b
// 256 threads, 64-row tile, thread = 4 strided rows x 8 cols.
// ---------------------------------------------------------------------------
__global__ __launch_bounds__(256) void linear_kernel(
    const float* __restrict__ X, const float* __restrict__ W,
    const float* __restrict__ bias, float* __restrict__ Y, int M)
{
    extern __shared__ float sm[];
    float* Ws = sm;            // 128*128
    float* Xs = sm + DD * DD;  // 64*PX

    int tid = threadIdx.x;
    int ty = tid >> 4, tx = tid & 15;

    for (int i = tid * 4; i < DD * DD; i += 256 * 4)
        *(float4*)(Ws + i) = *(const float4*)(W + i);

    float bv[8];
#pragma unroll
    for (int j = 0; j < 8; ++j) bv[j] = bias[tx * 8 + j];

    int base = blockIdx.x * 64;
    for (int i = tid; i < 64 * 32; i += 256) {
        int r = i >> 5, c4 = (i & 31) << 2;
        int row = base + r;
        float4 x = make_float4(0.f, 0.f, 0.f, 0.f);
        if (row < M) x = *(const float4*)(X + (size_t)row * DD + c4);
        *(float4*)(Xs + r * PX + c4) = x;
    }
    __syncthreads();

    float acc[4][8];
#pragma unroll
    for (int r = 0; r < 4; ++r)
#pragma unroll
        for (int j = 0; j < 8; ++j) acc[r][j] = 0.f;

#pragma unroll 4
    for (int k = 0; k < DD; ++k) {
        float w[8];
        *(float4*)(w)     = *(const float4*)(Ws + k * DD + tx * 8);
        *(float4*)(w + 4) = *(const float4*)(Ws + k * DD + tx * 8 + 4);
        float a[4];
#pragma unroll
        for (int r = 0; r < 4; ++r) a[r] = Xs[(ty + 16 * r) * PX + k];
#pragma unroll
        for (int r = 0; r < 4; ++r)
#pragma unroll
            for (int j = 0; j < 8; ++j) acc[r][j] = fmaf(a[r], w[j], acc[r][j]);
    }

#pragma unroll
    for (int r = 0; r < 4; ++r) {
        int row = base + ty + 16 * r;
        if (row < M) {
            float o[8];
#pragma unroll
            for (int j = 0; j < 8; ++j) o[j] = acc[r][j] + bv[j];
            *(float4*)(Y + (size_t)row * DD + tx * 8)     = ((float4*)o)[0];
            *(float4*)(Y + (size_t)row * DD + tx * 8 + 4) = ((float4*)o)[1];
        }
    }
}

// ---------------------------------------------------------------------------
// Edge pass 1: e = EF@We+be, m = EF@Wm+bm (fused GEMMs),
//              p = exp(m*(q[src]-k[dst]) + e)  [no max-sub needed, fp32 safe],
//              g_p <- p, g_den[dst] += p  (atomics).
// Persistent blocks, weights resident in smem. NE % 64 == 0 (no tail).
// ---------------------------------------------------------------------------
__global__ __launch_bounds__(256) void edge_pass1(
    const float* __restrict__ EF,
    const float* __restrict__ We, const float* __restrict__ be,
    const float* __restrict__ Wm, const float* __restrict__ bm,
    const int* __restrict__ src, const int* __restrict__ dst)
{
    extern __shared__ float sm[];
    float* WEs = sm;                // 128*128
    float* WMs = sm + DD * DD;      // 128*128
    float* Xs  = sm + 2 * DD * DD;  // 64*PX
    __shared__ int ssrc[64], sdst[64];

    int tid = threadIdx.x;
    int ty = tid >> 4, tx = tid & 15;

    for (int i = tid * 4; i < DD * DD; i += 256 * 4) {
        *(float4*)(WEs + i) = *(const float4*)(We + i);
        *(float4*)(WMs + i) = *(const float4*)(Wm + i);
    }
    float bev[8], bmv[8];
#pragma unroll
    for (int j = 0; j < 8; ++j) { bev[j] = be[tx * 8 + j]; bmv[j] = bm[tx * 8 + j]; }

    const int numTiles = NE / 64;  // 12500 exactly
    for (int t = blockIdx.x; t < numTiles; t += gridDim.x) {
        __syncthreads();  // protect Xs/ssrc reuse across iterations
        int base = t * 64;
        if (tid < 64) { ssrc[tid] = src[base + tid]; sdst[tid] = dst[base + tid]; }
        for (int i = tid; i < 64 * 32; i += 256) {
            int r = i >> 5, c4 = (i & 31) << 2;
            *(float4*)(Xs + r * PX + c4) =
                *(const float4*)(EF + (size_t)(base + r) * DD + c4);
        }
        __syncthreads();

        float ae[4][8], am[4][8];
#pragma unroll
        for (int r = 0; r < 4; ++r)
#pragma unroll
            for (int j = 0; j < 8; ++j) { ae[r][j] = 0.f; am[r][j] = 0.f; }

#pragma unroll 2
        for (int k = 0; k < DD; ++k) {
            float we[8], wm[8];
            *(float4*)(we)     = *(const float4*)(WEs + k * DD + tx * 8);
            *(float4*)(we + 4) = *(const float4*)(WEs + k * DD + tx * 8 + 4);
            *(float4*)(wm)     = *(const float4*)(WMs + k * DD + tx * 8);
            *(float4*)(wm + 4) = *(const float4*)(WMs + k * DD + tx * 8 + 4);
            float a[4];
#pragma unroll
            for (int r = 0; r < 4; ++r) a[r] = Xs[(ty + 16 * r) * PX + k];
#pragma unroll
            for (int r = 0; r < 4; ++r)
#pragma unroll
                for (int j = 0; j < 8; ++j) {
                    ae[r][j] = fmaf(a[r], we[j], ae[r][j]);
                    am[r][j] = fmaf(a[r], wm[j], am[r][j]);
                }
        }

#pragma unroll
        for (int r = 0; r < 4; ++r) {
            int el = ty + 16 * r;
            int e  = base + el;
            int s  = ssrc[el];
            int d2 = sdst[el];
            const float* qp = g_q + (size_t)s * DD + tx * 8;
            const float* kp = g_k + (size_t)d2 * DD + tx * 8;
            float qv[8], kv[8];
            *(float4*)(qv)     = __ldg((const float4*)(qp));
            *(float4*)(qv + 4) = __ldg((const float4*)(qp + 4));
            *(float4*)(kv)     = __ldg((const float4*)(kp));
            *(float4*)(kv + 4) = __ldg((const float4*)(kp + 4));
            float p[8];
#pragma unroll
            for (int j = 0; j < 8; ++j) {
                float sc = fmaf(am[r][j] + bmv[j], qv[j] - kv[j], ae[r][j] + bev[j]);
                p[j] = __expf(sc);
            }
            *(float4*)(g_p + (size_t)e * DD + tx * 8)     = ((float4*)p)[0];
            *(float4*)(g_p + (size_t)e * DD + tx * 8 + 4) = ((float4*)p)[1];
            float* dp = g_den + (size_t)d2 * DD + tx * 8;
#pragma unroll
            for (int j = 0; j < 8; ++j) atomicAdd(dp + j, p[j]);
        }
    }
}

// ---------------------------------------------------------------------------
// Edge pass 2: h[dst] += v[src] * p / den[dst]. One thread per (edge, 4 ch).
// ---------------------------------------------------------------------------
__global__ __launch_bounds__(256) void edge_pass2(
    const int* __restrict__ src, const int* __restrict__ dst)
{
    long long g = (long long)blockIdx.x * blockDim.x + threadIdx.x;
    int e = (int)(g >> 5);
    if (e >= NE) return;
    int c = ((int)g & 31) << 2;
    int s  = __ldg(src + e);
    int d2 = __ldg(dst + e);
    float4 p  = *(const float4*)(g_p + (size_t)e * DD + c);
    float4 v  = __ldg((const float4*)(g_v + (size_t)s * DD + c));
    float4 dn = __ldg((const float4*)(g_den + (size_t)d2 * DD + c));
    float* hp = g_h + (size_t)d2 * DD + c;
    atomicAdd(hp + 0, v.x * (p.x / dn.x));
    atomicAdd(hp + 1, v.y * (p.y / dn.y));
    atomicAdd(hp + 2, v.z * (p.z / dn.z));
    atomicAdd(hp + 3, v.w * (p.w / dn.w));
}

// ---------------------------------------------------------------------------
// Final: x = h + node_feats; u = mish(x@Wf1+bf1); t = LN(u)*g_f+b_f;
//        y = t@Wf2+bf2; out = LN(y)*g_ln+b_ln.
// Same tiling as linear_kernel; LN reductions via 16-lane shfl groups.
// ---------------------------------------------------------------------------
__global__ __launch_bounds__(256) void final_kernel(
    const float* __restrict__ NF,
    const float* __restrict__ Wf1, const float* __restrict__ bf1,
    const float* __restrict__ gf,  const float* __restrict__ bff,
    const float* __restrict__ Wf2, const float* __restrict__ bf2,
    const float* __restrict__ gln, const float* __restrict__ bln,
    float* __restrict__ out)
{
    extern __shared__ float sm[];
    float* W1s = sm;
    float* W2s = sm + DD * DD;
    float* Xs  = sm + 2 * DD * DD;  // 64*PX

    int tid = threadIdx.x;
    int ty = tid >> 4, tx = tid & 15;

    for (int i = tid * 4; i < DD * DD; i += 256 * 4) {
        *(float4*)(W1s + i) = *(const float4*)(Wf1 + i);
        *(float4*)(W2s + i) = *(const float4*)(Wf2 + i);
    }
    float b1v[8], b2v[8], gfv[8], bfv[8], glv[8], blv[8];
#pragma unroll
    for (int j = 0; j < 8; ++j) {
        int c = tx * 8 + j;
        b1v[j] = bf1[c]; b2v[j] = bf2[c];
        gfv[j] = gf[c];  bfv[j] = bff[c];
        glv[j] = gln[c]; blv[j] = bln[c];
    }

    const int numTiles = (NN + 63) / 64;
    for (int t = blockIdx.x; t < numTiles; t += gridDim.x) {
        __syncthreads();
        int base = t * 64;
        for (int i = tid; i < 64 * 32; i += 256) {
            int r = i >> 5, c4 = (i & 31) << 2;
            int row = base + r;
            float4 x = make_float4(0.f, 0.f, 0.f, 0.f);
            if (row < NN) {
                float4 hh = *(const float4*)(g_h + (size_t)row * DD + c4);
                float4 nf = *(const float4*)(NF + (size_t)row * DD + c4);
                x = make_float4(hh.x + nf.x, hh.y + nf.y, hh.z + nf.z, hh.w + nf.w);
            }
            *(float4*)(Xs + r * PX + c4) = x;
        }
        __syncthreads();

        // GEMM1
        float u[4][8];
#pragma unroll
        for (int r = 0; r < 4; ++r)
#pragma unroll
            for (int j = 0; j < 8; ++j) u[r][j] = 0.f;
#pragma unroll 4
        for (int k = 0; k < DD; ++k) {
            float w[8];
            *(float4*)(w)     = *(const float4*)(W1s + k * DD + tx * 8);
            *(float4*)(w + 4) = *(const float4*)(W1s + k * DD + tx * 8 + 4);
            float a[4];
#pragma unroll
            for (int r = 0; r < 4; ++r) a[r] = Xs[(ty + 16 * r) * PX + k];
#pragma unroll
            for (int r = 0; r < 4; ++r)
#pragma unroll
                for (int j = 0; j < 8; ++j) u[r][j] = fmaf(a[r], w[j], u[r][j]);
        }
        // mish + layernorm(g_f, b_f)
#pragma unroll
        for (int r = 0; r < 4; ++r) {
#pragma unroll
            for (int j = 0; j < 8; ++j) {
                float x = u[r][j] + b1v[j];
                float sp = log1pf(expf(x));       // softplus
                u[r][j] = x * tanhf(sp);          // mish
            }
            float s1 = 0.f, s2 = 0.f;
#pragma unroll
            for (int j = 0; j < 8; ++j) { s1 += u[r][j]; s2 += u[r][j] * u[r][j]; }
#pragma unroll
            for (int mmask = 8; mmask > 0; mmask >>= 1) {
                s1 += __shfl_xor_sync(0xffffffffu, s1, mmask);
                s2 += __shfl_xor_sync(0xffffffffu, s2, mmask);
            }
            float mean = s1 * (1.f / 128.f);
            float var  = s2 * (1.f / 128.f) - mean * mean;
            float inv  = rsqrtf(var + 1e-5f);
#pragma unroll
            for (int j = 0; j < 8; ++j)
                u[r][j] = (u[r][j] - mean) * inv * gfv[j] + bfv[j];
        }
        __syncthreads();  // all GEMM1 reads of Xs done
#pragma unroll
        for (int r = 0; r < 4; ++r) {
            *(float4*)(Xs + (ty + 16 * r) * PX + tx * 8)     = ((float4*)u[r])[0];
            *(float4*)(Xs + (ty + 16 * r) * PX + tx * 8 + 4) = ((float4*)u[r])[1];
        }
        __syncthreads();

        // GEMM2
        float y[4][8];
#pragma unroll
        for (int r = 0; r < 4; ++r)
#pragma unroll
            for (int j = 0; j < 8; ++j) y[r][j] = 0.f;
#pragma unroll 4
        for (int k = 0; k < DD; ++k) {
            float w[8];
            *(float4*)(w)     = *(const float4*)(W2s + k * DD + tx * 8);
            *(float4*)(w + 4) = *(const float4*)(W2s + k * DD + tx * 8 + 4);
            float a[4];
#pragma unroll
            for (int r = 0; r < 4; ++r) a[r] = Xs[(ty + 16 * r) * PX + k];
#pragma unroll
            for (int r = 0; r < 4; ++r)
#pragma unroll
                for (int j = 0; j < 8; ++j) y[r][j] = fmaf(a[r], w[j], y[r][j]);
        }
        // + bias, layernorm(g_ln, b_ln), store
#pragma unroll
        for (int r = 0; r < 4; ++r) {
#pragma unroll
            for (int j = 0; j < 8; ++j) y[r][j] += b2v[j];
            float s1 = 0.f, s2 = 0.f;
#pragma unroll
            for (int j = 0; j < 8; ++j) { s1 += y[r][j]; s2 += y[r][j] * y[r][j]; }
#pragma unroll
            for (int mmask = 8; mmask > 0; mmask >>= 1) {
                s1 += __shfl_xor_sync(0xffffffffu, s1, mmask);
                s2 += __shfl_xor_sync(0xffffffffu, s2, mmask);
            }
            float mean = s1 * (1.f / 128.f);
            float var  = s2 * (1.f / 128.f) - mean * mean;
            float inv  = rsqrtf(var + 1e-5f);
            int row = base + ty + 16 * r;
            if (row < NN) {
                float o[8];
#pragma unroll
                for (int j = 0; j < 8; ++j)
                    o[j] = (y[r][j] - mean) * inv * glv[j] + blv[j];
                *(float4*)(out + (size_t)row * DD + tx * 8)     = ((float4*)o)[0];
                *(float4*)(out + (size_t)row * DD + tx * 8 + 4) = ((float4*)o)[1];
            }
        }
    }
}

// ---------------------------------------------------------------------------
extern "C" void kernel_launch(void* const* d_in, const int* in_sizes, int n_in,
                              void* d_out, int out_size)
{
    const float* node_feats = (const float*)d_in[0];
    const float* edge_feats = (const float*)d_in[1];
    const int*   src = (const int*)d_in[2];
    const int*   dst = (const int*)d_in[3];
    const float* Wq = (const float*)d_in[4];  const float* bq = (const float*)d_in[5];
    const float* Wk = (const float*)d_in[6];  const float* bk = (const float*)d_in[7];
    const float* Wv = (const float*)d_in[8];  const float* bv = (const float*)d_in[9];
    const float* We = (const float*)d_in[10]; const float* be = (const float*)d_in[11];
    const float* Wm = (const float*)d_in[12]; const float* bm = (const float*)d_in[13];
    const float* Wf1 = (const float*)d_in[14]; const float* bf1 = (const float*)d_in[15];
    const float* g_f = (const float*)d_in[16]; const float* b_f = (const float*)d_in[17];
    const float* Wf2 = (const float*)d_in[18]; const float* bf2 = (const float*)d_in[19];
    const float* g_ln = (const float*)d_in[20]; const float* b_ln = (const float*)d_in[21];
    float* out = (float*)d_out;

    void *pden, *ph;
    cudaGetSymbolAddress(&pden, g_den);
    cudaGetSymbolAddress(&ph, g_h);
    void *pq, *pk, *pv;
    cudaGetSymbolAddress(&pq, g_q);
    cudaGetSymbolAddress(&pk, g_k);
    cudaGetSymbolAddress(&pv, g_v);

    const size_t LIN_SMEM = (size_t)(DD * DD + 64 * PX) * sizeof(float);      // ~97 KB
    const size_t BIG_SMEM = (size_t)(2 * DD * DD + 64 * PX) * sizeof(float);  // ~161 KB
    cudaFuncSetAttribute(linear_kernel, cudaFuncAttributeMaxDynamicSharedMemorySize, (int)LIN_SMEM);
    cudaFuncSetAttribute(edge_pass1,    cudaFuncAttributeMaxDynamicSharedMemorySize, (int)BIG_SMEM);
    cudaFuncSetAttribute(final_kernel,  cudaFuncAttributeMaxDynamicSharedMemorySize, (int)BIG_SMEM);

    cudaMemsetAsync(pden, 0, (size_t)NN * DD * sizeof(float), 0);
    cudaMemsetAsync(ph,   0, (size_t)NN * DD * sizeof(float), 0);

    // edge_feats passthrough output (independent; overlap with compute)
    cudaMemcpyAsync(out + (size_t)NN * DD, edge_feats,
                    (size_t)NE * DD * sizeof(float), cudaMemcpyDeviceToDevice, 0);

    int linGrid = (NN + 63) / 64;  // 782
    linear_kernel<<<linGrid, 256, LIN_SMEM>>>(node_feats, Wq, bq, (float*)pq, NN);
    linear_kernel<<<linGrid, 256, LIN_SMEM>>>(node_feats, Wk, bk, (float*)pk, NN);
    linear_kernel<<<linGrid, 256, LIN_SMEM>>>(node_feats, Wv, bv, (float*)pv, NN);

    edge_pass1<<<152, 256, BIG_SMEM>>>(edge_feats, We, be, Wm, bm, src, dst);

    long long p2threads = (long long)NE * 32;
    int p2blocks = (int)((p2threads + 255) / 256);  // 100000
    edge_pass2<<<p2blocks, 256>>>(src, dst);

    final_kernel<<<152, 256, BIG_SMEM>>>(node_feats, Wf1, bf1, g_f, b_f,
                                         Wf2, bf2, g_ln, b_ln, out);
}

// round 3
// speedup vs baseline: 2.8206x; 2.8206x over previous
#include <cuda_runtime.h>
#include <cstdint>
#include <math.h>

#define NN 50000
#define NE 800000
#define PIT 132  // smem row pitch in 4B words: 132%32=4 -> conflict-free frag loads

// ----------------------------- scratch globals -----------------------------
__device__ float g_q[NN * 128];
__device__ float g_k[NN * 128];
__device__ float g_v[NN * 128];
__device__ float g_den[NN * 128];
__device__ float g_h[NN * 128];

// weights transposed to [n][k], tf32-rounded bit patterns
__device__ uint32_t g_WtQ[128 * 128];
__device__ uint32_t g_WtK[128 * 128];
__device__ uint32_t g_WtV[128 * 128];
__device__ uint32_t g_WtF1[128 * 128];
__device__ uint32_t g_WtF2g[128 * 128];
__device__ uint32_t g_WtEM[256 * 128];  // channel-permuted [We|Wm]
__device__ float g_vb[128];
__device__ float g_vg[128];

// ----------------------------- helpers -------------------------------------
__device__ __forceinline__ uint32_t rna(float x) {
    uint32_t r;
    asm("cvt.rna.tf32.f32 %0, %1;" : "=r"(r) : "f"(x));
    return r;
}

__device__ __forceinline__ void mma8(float* c, const uint32_t* a, const uint32_t* b) {
    asm volatile(
        "mma.sync.aligned.m16n8k8.row.col.f32.tf32.tf32.f32 "
        "{%0,%1,%2,%3}, {%4,%5,%6,%7}, {%8,%9}, {%0,%1,%2,%3};"
        : "+f"(c[0]), "+f"(c[1]), "+f"(c[2]), "+f"(c[3])
        : "r"(a[0]), "r"(a[1]), "r"(a[2]), "r"(a[3]), "r"(b[0]), "r"(b[1]));
}

__device__ __forceinline__ float mishf(float x) {
    float sp = (x > 20.f) ? x : log1pf(__expf(x));
    return x * tanhf(sp);
}

// ----------------------------- prep kernels --------------------------------
// EM column permutation: j in [0,256) -> (warp_n=j>>6, nt=(j>>3)&7, t=(j>>1)&3,
// par=j&1), channel = warp_n*32 + t*8 + nt. Gives each MMA thread 8 consecutive
// channels with (e,m) adjacent in its accumulator fragment.
__global__ void prep_T(const float* __restrict__ Wq, const float* __restrict__ Wk,
                       const float* __restrict__ Wv, const float* __restrict__ We,
                       const float* __restrict__ Wm, const float* __restrict__ Wf1,
                       const float* __restrict__ Wf2, const float* __restrict__ gf) {
    int k = blockIdx.x, n = threadIdx.x;
    int s = k * 128 + n, d = n * 128 + k;
    g_WtQ[d] = rna(Wq[s]);
    g_WtK[d] = rna(Wk[s]);
    g_WtV[d] = rna(Wv[s]);
    g_WtF1[d] = rna(Wf1[s]);
    g_WtF2g[d] = rna(gf[k] * Wf2[s]);
#pragma unroll
    for (int jj = 0; jj < 2; jj++) {
        int j = n + jj * 128;
        int wn = j >> 6, wi = j & 63, nt = wi >> 3, rem = wi & 7, tt = rem >> 1, par = rem & 1;
        int ch = wn * 32 + tt * 8 + nt;
        const float* W = par ? Wm : We;
        g_WtEM[j * 128 + k] = rna(W[k * 128 + ch]);
    }
}

__global__ void prep_V(const float* __restrict__ Wf2, const float* __restrict__ bf,
                       const float* __restrict__ gf, const float* __restrict__ bf2) {
    int n = threadIdx.x;
    float a = 0.f, b = 0.f;
    for (int k = 0; k < 128; k++) {
        float w = Wf2[k * 128 + n];
        a = fmaf(bf[k], w, a);
        b = fmaf(gf[k], w, b);
    }
    g_vb[n] = bf2[n] + a;
    g_vg[n] = b;
}

// ----------------------------- linear: Y = X@W + b -------------------------
// 256 thr = 8 warps (2 m x 4 n), warp tile m64 x n32, tf32 mma.sync.
__global__ __launch_bounds__(256, 1) void linear_tc(
    const float* __restrict__ X, const uint32_t* __restrict__ Bt,
    const float* __restrict__ bias, float* __restrict__ Y, int M) {
    extern __shared__ __align__(16) uint32_t sm[];
    uint32_t* sA = sm;            // 128*PIT
    uint32_t* sB = sm + 128 * PIT;

    int tid = threadIdx.x, w = tid >> 5, lane = tid & 31;
    int wm = w >> 2, wn = w & 3, g = lane >> 2, t = lane & 3;

    for (int i = tid; i < 128 * 32; i += 256) {
        int r = i >> 5, c = (i & 31) * 4;
        *(uint4*)(sB + r * PIT + c) = *(const uint4*)(Bt + r * 128 + c);
    }
    float bc[4][2];
#pragma unroll
    for (int nt = 0; nt < 4; nt++) {
        int col = wn * 32 + nt * 8 + t * 2;
        bc[nt][0] = __ldg(bias + col);
        bc[nt][1] = __ldg(bias + col + 1);
    }

    int nT = (M + 127) >> 7;
    for (int tt = blockIdx.x; tt < nT; tt += gridDim.x) {
        __syncthreads();
        int base = tt << 7;
        for (int i = tid; i < 128 * 32; i += 256) {
            int r = i >> 5, c = (i & 31) * 4;
            int row = base + r;
            uint4 u = make_uint4(0u, 0u, 0u, 0u);
            if (row < M) {
                float4 x = *(const float4*)(X + (size_t)row * 128 + c);
                u.x = rna(x.x); u.y = rna(x.y); u.z = rna(x.z); u.w = rna(x.w);
            }
            *(uint4*)(sA + r * PIT + c) = u;
        }
        __syncthreads();

        float c_[4][4][4];
#pragma unroll
        for (int mt = 0; mt < 4; mt++)
#pragma unroll
            for (int nt = 0; nt < 4; nt++)
#pragma unroll
                for (int i = 0; i < 4; i++) c_[mt][nt][i] = 0.f;

#pragma unroll
        for (int k0 = 0; k0 < 128; k0 += 8) {
            uint32_t a[4][4], b[4][2];
#pragma unroll
            for (int mt = 0; mt < 4; mt++) {
                int r = wm * 64 + mt * 16 + g;
                a[mt][0] = sA[r * PIT + k0 + t];
                a[mt][1] = sA[(r + 8) * PIT + k0 + t];
                a[mt][2] = sA[r * PIT + k0 + t + 4];
                a[mt][3] = sA[(r + 8) * PIT + k0 + t + 4];
            }
#pragma unroll
            for (int nt = 0; nt < 4; nt++) {
                int n = wn * 32 + nt * 8 + g;
                b[nt][0] = sB[n * PIT + k0 + t];
                b[nt][1] = sB[n * PIT + k0 + t + 4];
            }
#pragma unroll
            for (int mt = 0; mt < 4; mt++)
#pragma unroll
                for (int nt = 0; nt < 4; nt++) mma8(c_[mt][nt], a[mt], b[nt]);
        }

#pragma unroll
        for (int mt = 0; mt < 4; mt++) {
            int row = base + wm * 64 + mt * 16 + g;
#pragma unroll
            for (int nt = 0; nt < 4; nt++) {
                int col = wn * 32 + nt * 8 + t * 2;
                if (row < M) {
                    float2 o = make_float2(c_[mt][nt][0] + bc[nt][0], c_[mt][nt][1] + bc[nt][1]);
                    *(float2*)(Y + (size_t)row * 128 + col) = o;
                }
                if (row + 8 < M) {
                    float2 o = make_float2(c_[mt][nt][2] + bc[nt][0], c_[mt][nt][3] + bc[nt][1]);
                    *(float2*)(Y + (size_t)(row + 8) * 128 + col) = o;
                }
            }
        }
    }
}

// ----------------------------- fused edge pass ------------------------------
// [e|m](perm) = EF @ WtEM ; p = exp((m+bm)*(q[src]-k[dst]) + e+be)
// den[dst] += p ; h[dst] += p*v[src]  (float4 atomics).
// 256 thr = 8 warps (2 m x 4 n), warp tile m64 x n64 over N=256.
__global__ __launch_bounds__(256, 1) void edge_tc(
    const float* __restrict__ EF, const float* __restrict__ be,
    const float* __restrict__ bm, const int* __restrict__ src,
    const int* __restrict__ dst) {
    extern __shared__ __align__(16) uint32_t sm[];
    uint32_t* sA = sm;                 // 128*PIT
    uint32_t* sB = sm + 128 * PIT;     // 256*PIT
    int* ssrc = (int*)(sm + 128 * PIT + 256 * PIT);
    int* sdst = ssrc + 128;

    int tid = threadIdx.x, w = tid >> 5, lane = tid & 31;
    int wm = w >> 2, wn = w & 3, g = lane >> 2, t = lane & 3;
    int chb = wn * 32 + t * 8;

    for (int i = tid; i < 256 * 32; i += 256) {
        int r = i >> 5, c = (i & 31) * 4;
        *(uint4*)(sB + r * PIT + c) = *(const uint4*)(g_WtEM + r * 128 + c);
    }
    float bea[8], bma[8];
    *(float4*)(bea) = __ldg((const float4*)(be + chb));
    *(float4*)(bea + 4) = __ldg((const float4*)(be + chb + 4));
    *(float4*)(bma) = __ldg((const float4*)(bm + chb));
    *(float4*)(bma + 4) = __ldg((const float4*)(bm + chb + 4));

    const int nT = NE / 128;  // 6250 exact
    for (int tt = blockIdx.x; tt < nT; tt += gridDim.x) {
        __syncthreads();
        int base = tt << 7;
        if (tid < 128) {
            ssrc[tid] = src[base + tid];
            sdst[tid] = dst[base + tid];
        }
        for (int i = tid; i < 128 * 32; i += 256) {
            int r = i >> 5, c = (i & 31) * 4;
            float4 x = *(const float4*)(EF + (size_t)(base + r) * 128 + c);
            uint4 u;
            u.x = rna(x.x); u.y = rna(x.y); u.z = rna(x.z); u.w = rna(x.w);
            *(uint4*)(sA + r * PIT + c) = u;
        }
        __syncthreads();

        float c_[4][8][4];
#pragma unroll
        for (int mt = 0; mt < 4; mt++)
#pragma unroll
            for (int nt = 0; nt < 8; nt++)
#pragma unroll
                for (int i = 0; i < 4; i++) c_[mt][nt][i] = 0.f;

#pragma unroll
        for (int k0 = 0; k0 < 128; k0 += 8) {
            uint32_t a[4][4], b[8][2];
#pragma unroll
            for (int mt = 0; mt < 4; mt++) {
                int r = wm * 64 + mt * 16 + g;
                a[mt][0] = sA[r * PIT + k0 + t];
                a[mt][1] = sA[(r + 8) * PIT + k0 + t];
                a[mt][2] = sA[r * PIT + k0 + t + 4];
                a[mt][3] = sA[(r + 8) * PIT + k0 + t + 4];
            }
#pragma unroll
            for (int nt = 0; nt < 8; nt++) {
                int n = wn * 64 + nt * 8 + g;
                b[nt][0] = sB[n * PIT + k0 + t];
                b[nt][1] = sB[n * PIT + k0 + t + 4];
            }
#pragma unroll
            for (int mt = 0; mt < 4; mt++)
#pragma unroll
                for (int nt = 0; nt < 8; nt++) mma8(c_[mt][nt], a[mt], b[nt]);
        }

        // epilogue: thread owns channels [chb, chb+8) for rows (mt,g/g+8)
#pragma unroll
        for (int mt = 0; mt < 4; mt++) {
#pragma unroll
            for (int rs = 0; rs < 2; rs++) {
                int rl = wm * 64 + mt * 16 + g + rs * 8;
                int s = ssrc[rl], d = sdst[rl];
                float qa[8], ka[8], va[8];
                const float4* qp = (const float4*)(g_q + (size_t)s * 128 + chb);
                const float4* kp = (const float4*)(g_k + (size_t)d * 128 + chb);
                const float4* vp = (const float4*)(g_v + (size_t)s * 128 + chb);
                *(float4*)(qa) = __ldg(qp);     *(float4*)(qa + 4) = __ldg(qp + 1);
                *(float4*)(ka) = __ldg(kp);     *(float4*)(ka + 4) = __ldg(kp + 1);
                *(float4*)(va) = __ldg(vp);     *(float4*)(va + 4) = __ldg(vp + 1);
                float p[8], pv[8];
#pragma unroll
                for (int nt = 0; nt < 8; nt++) {
                    float ev = c_[mt][nt][rs * 2] + bea[nt];
                    float mv = c_[mt][nt][rs * 2 + 1] + bma[nt];
                    p[nt] = __expf(fmaf(mv, qa[nt] - ka[nt], ev));
                    pv[nt] = p[nt] * va[nt];
                }
                float4* dp = (float4*)(g_den + (size_t)d * 128 + chb);
                float4* hp = (float4*)(g_h + (size_t)d * 128 + chb);
                atomicAdd(dp, make_float4(p[0], p[1], p[2], p[3]));
                atomicAdd(dp + 1, make_float4(p[4], p[5], p[6], p[7]));
                atomicAdd(hp, make_float4(pv[0], pv[1], pv[2], pv[3]));
                atomicAdd(hp + 1, make_float4(pv[4], pv[5], pv[6], pv[7]));
            }
        }
    }
}

// ----------------------------- final fused MLP ------------------------------
// x = h/den + NF ; u = mish(x@Wf1+bf1) ; LN1 folded through GEMM2:
// y = inv1*(u@(g_f.*Wf2)) + vb - mu1*inv1*vg ; out = LN2(y)*g_ln + b_ln
__global__ __launch_bounds__(256, 1) void final_tc(
    const float* __restrict__ NF, const float* __restrict__ bf1,
    const float* __restrict__ gln, const float* __restrict__ bln,
    float* __restrict__ out) {
    extern __shared__ __align__(16) uint32_t sm[];
    uint32_t* sA = sm;
    uint32_t* sB1 = sm + 128 * PIT;
    uint32_t* sB2 = sm + 2 * 128 * PIT;
    float* smu = (float*)(sm + 3 * 128 * PIT);
    float* sinv = smu + 128;
    float* sgl = sinv + 128;
    float* sbl = sgl + 128;

    int tid = threadIdx.x, w = tid >> 5, lane = tid & 31;
    int wm = w >> 2, wn = w & 3, g = lane >> 2, t = lane & 3;

    for (int i = tid; i < 128 * 32; i += 256) {
        int r = i >> 5, c = (i & 31) * 4;
        *(uint4*)(sB1 + r * PIT + c) = *(const uint4*)(g_WtF1 + r * 128 + c);
        *(uint4*)(sB2 + r * PIT + c) = *(const uint4*)(g_WtF2g + r * 128 + c);
    }
    if (tid < 128) {
        sgl[tid] = gln[tid];
        sbl[tid] = bln[tid];
    }
    float b1c[4][2], vbc[4][2], vgc[4][2];
#pragma unroll
    for (int nt = 0; nt < 4; nt++) {
        int col = wn * 32 + nt * 8 + t * 2;
        b1c[nt][0] = __ldg(bf1 + col);   b1c[nt][1] = __ldg(bf1 + col + 1);
        vbc[nt][0] = g_vb[col];          vbc[nt][1] = g_vb[col + 1];
        vgc[nt][0] = g_vg[col];          vgc[nt][1] = g_vg[col + 1];
    }

    int srow = tid >> 1, shalf = tid & 1;
    const int nT = (NN + 127) >> 7;
    for (int tt = blockIdx.x; tt < nT; tt += gridDim.x) {
        __syncthreads();
        int base = tt << 7;
        for (int i = tid; i < 128 * 32; i += 256) {
            int r = i >> 5, c = (i & 31) * 4;
            int row = base + r;
            uint4 u = make_uint4(0u, 0u, 0u, 0u);
            if (row < NN) {
                float4 hh = *(const float4*)(g_h + (size_t)row * 128 + c);
                float4 dn = *(const float4*)(g_den + (size_t)row * 128 + c);
                float4 nf = *(const float4*)(NF + (size_t)row * 128 + c);
                u.x = rna((dn.x > 0.f ? hh.x / dn.x : 0.f) + nf.x);
                u.y = rna((dn.y > 0.f ? hh.y / dn.y : 0.f) + nf.y);
                u.z = rna((dn.z > 0.f ? hh.z / dn.z : 0.f) + nf.z);
                u.w = rna((dn.w > 0.f ? hh.w / dn.w : 0.f) + nf.w);
            }
            *(uint4*)(sA + r * PIT + c) = u;
        }
        __syncthreads();

        // GEMM1: u = x @ Wf1
        float c_[4][4][4];
#pragma unroll
        for (int mt = 0; mt < 4; mt++)
#pragma unroll
            for (int nt = 0; nt < 4; nt++)
#pragma unroll
                for (int i = 0; i < 4; i++) c_[mt][nt][i] = 0.f;
#pragma unroll
        for (int k0 = 0; k0 < 128; k0 += 8) {
            uint32_t a[4][4], b[4][2];
#pragma unroll
            for (int mt = 0; mt < 4; mt++) {
                int r = wm * 64 + mt * 16 + g;
                a[mt][0] = sA[r * PIT + k0 + t];
                a[mt][1] = sA[(r + 8) * PIT + k0 + t];
                a[mt][2] = sA[r * PIT + k0 + t + 4];
                a[mt][3] = sA[(r + 8) * PIT + k0 + t + 4];
            }
#pragma unroll
            for (int nt = 0; nt < 4; nt++) {
                int n = wn * 32 + nt * 8 + g;
                b[nt][0] = sB1[n * PIT + k0 + t];
                b[nt][1] = sB1[n * PIT + k0 + t + 4];
            }
#pragma unroll
            for (int mt = 0; mt < 4; mt++)
#pragma unroll
                for (int nt = 0; nt < 4; nt++) mma8(c_[mt][nt], a[mt], b[nt]);
        }
        __syncthreads();  // all reads of sA(x) done

        // mish, write u (tf32) back to sA
#pragma unroll
        for (int mt = 0; mt < 4; mt++) {
            int r0 = wm * 64 + mt * 16 + g;
#pragma unroll
            for (int nt = 0; nt < 4; nt++) {
                int col = wn * 32 + nt * 8 + t * 2;
                uint2 u0, u1;
                u0.x = rna(mishf(c_[mt][nt][0] + b1c[nt][0]));
                u0.y = rna(mishf(c_[mt][nt][1] + b1c[nt][1]));
                u1.x = rna(mishf(c_[mt][nt][2] + b1c[nt][0]));
                u1.y = rna(mishf(c_[mt][nt][3] + b1c[nt][1]));
                *(uint2*)(sA + r0 * PIT + col) = u0;
                *(uint2*)(sA + (r0 + 8) * PIT + col) = u1;
            }
        }
        __syncthreads();

        // LN1 row stats (2 threads per row)
        {
            float s1 = 0.f, s2 = 0.f;
            const uint32_t* rp = sA + srow * PIT + shalf * 64;
#pragma unroll
            for (int i = 0; i < 16; i++) {
                uint4 uu = *(const uint4*)(rp + i * 4);
                float x0 = __uint_as_float(uu.x), x1 = __uint_as_float(uu.y);
                float x2 = __uint_as_float(uu.z), x3 = __uint_as_float(uu.w);
                s1 += x0 + x1 + x2 + x3;
                s2 += x0 * x0 + x1 * x1 + x2 * x2 + x3 * x3;
            }
            s1 += __shfl_xor_sync(0xffffffffu, s1, 1);
            s2 += __shfl_xor_sync(0xffffffffu, s2, 1);
            if (shalf == 0) {
                float mu = s1 * (1.f / 128.f);
                smu[srow] = mu;
                sinv[srow] = rsqrtf(s2 * (1.f / 128.f) - mu * mu + 1e-5f);
            }
        }
        __syncthreads();

        // GEMM2: acc = u @ (g_f .* Wf2)
        float c2[4][4][4];
#pragma unroll
        for (int mt = 0; mt < 4; mt++)
#pragma unroll
            for (int nt = 0; nt < 4; nt++)
#pragma unroll
                for (int i = 0; i < 4; i++) c2[mt][nt][i] = 0.f;
#pragma unroll
        for (int k0 = 0; k0 < 128; k0 += 8) {
            uint32_t a[4][4], b[4][2];
#pragma unroll
            for (int mt = 0; mt < 4; mt++) {
                int r = wm * 64 + mt * 16 + g;
                a[mt][0] = sA[r * PIT + k0 + t];
                a[mt][1] = sA[(r + 8) * PIT + k0 + t];
                a[mt][2] = sA[r * PIT + k0 + t + 4];
                a[mt][3] = sA[(r + 8) * PIT + k0 + t + 4];
            }
#pragma unroll
            for (int nt = 0; nt < 4; nt++) {
                int n = wn * 32 + nt * 8 + g;
                b[nt][0] = sB2[n * PIT + k0 + t];
                b[nt][1] = sB2[n * PIT + k0 + t + 4];
            }
#pragma unroll
            for (int mt = 0; mt < 4; mt++)
#pragma unroll
                for (int nt = 0; nt < 4; nt++) mma8(c2[mt][nt], a[mt], b[nt]);
        }
        __syncthreads();  // all reads of sA(u) done

        // y = inv1*acc + vb - mu1*inv1*vg, write y (f32 bits) to sA
#pragma unroll
        for (int mt = 0; mt < 4; mt++) {
            int r0 = wm * 64 + mt * 16 + g;
            float mu0 = smu[r0], iv0 = sinv[r0];
            float mu8 = smu[r0 + 8], iv8 = sinv[r0 + 8];
#pragma unroll
            for (int nt = 0; nt < 4; nt++) {
                int col = wn * 32 + nt * 8 + t * 2;
                uint2 y0, y1;
                y0.x = __float_as_uint(iv0 * c2[mt][nt][0] + vbc[nt][0] - mu0 * iv0 * vgc[nt][0]);
                y0.y = __float_as_uint(iv0 * c2[mt][nt][1] + vbc[nt][1] - mu0 * iv0 * vgc[nt][1]);
                y1.x = __float_as_uint(iv8 * c2[mt][nt][2] + vbc[nt][0] - mu8 * iv8 * vgc[nt][0]);
                y1.y = __float_as_uint(iv8 * c2[mt][nt][3] + vbc[nt][1] - mu8 * iv8 * vgc[nt][1]);
                *(uint2*)(sA + r0 * PIT + col) = y0;
                *(uint2*)(sA + (r0 + 8) * PIT + col) = y1;
            }
        }
        __syncthreads();

        // LN2 row stats
        {
            float s1 = 0.f, s2 = 0.f;
            const uint32_t* rp = sA + srow * PIT + shalf * 64;
#pragma unroll
            for (int i = 0; i < 16; i++) {
                uint4 uu = *(const uint4*)(rp + i * 4);
                float x0 = __uint_as_float(uu.x), x1 = __uint_as_float(uu.y);
                float x2 = __uint_as_float(uu.z), x3 = __uint_as_float(uu.w);
                s1 += x0 + x1 + x2 + x3;
                s2 += x0 * x0 + x1 * x1 + x2 * x2 + x3 * x3;
            }
            s1 += __shfl_xor_sync(0xffffffffu, s1, 1);
            s2 += __shfl_xor_sync(0xffffffffu, s2, 1);
            if (shalf == 0) {
                float mu = s1 * (1.f / 128.f);
                smu[srow] = mu;
                sinv[srow] = rsqrtf(s2 * (1.f / 128.f) - mu * mu + 1e-5f);
            }
        }
        __syncthreads();

        // final store
        {
            int row = base + srow;
            if (row < NN) {
                float mu = smu[srow], iv = sinv[srow];
                const uint32_t* rp = sA + srow * PIT + shalf * 64;
#pragma unroll
                for (int i = 0; i < 16; i++) {
                    int col = shalf * 64 + i * 4;
                    uint4 uu = *(const uint4*)(rp + i * 4);
                    float4 o;
                    o.x = (__uint_as_float(uu.x) - mu) * iv * sgl[col + 0] + sbl[col + 0];
                    o.y = (__uint_as_float(uu.y) - mu) * iv * sgl[col + 1] + sbl[col + 1];
                    o.z = (__uint_as_float(uu.z) - mu) * iv * sgl[col + 2] + sbl[col + 2];
                    o.w = (__uint_as_float(uu.w) - mu) * iv * sgl[col + 3] + sbl[col + 3];
                    *(float4*)(out + (size_t)row * 128 + col) = o;
                }
            }
        }
    }
}

// ---------------------------------------------------------------------------
extern "C" void kernel_launch(void* const* d_in, const int* in_sizes, int n_in,
                              void* d_out, int out_size) {
    const float* node_feats = (const float*)d_in[0];
    const float* edge_feats = (const float*)d_in[1];
    const int* src = (const int*)d_in[2];
    const int* dst = (const int*)d_in[3];
    const float* Wq = (const float*)d_in[4];
    const float* bq = (const float*)d_in[5];
    const float* Wk = (const float*)d_in[6];
    const float* bk = (const float*)d_in[7];
    const float* Wv = (const float*)d_in[8];
    const float* bv = (const float*)d_in[9];
    const float* We = (const float*)d_in[10];
    const float* be = (const float*)d_in[11];
    const float* Wm = (const float*)d_in[12];
    const float* bm = (const float*)d_in[13];
    const float* Wf1 = (const float*)d_in[14];
    const float* bf1 = (const float*)d_in[15];
    const float* g_f = (const float*)d_in[16];
    const float* b_f = (const float*)d_in[17];
    const float* Wf2 = (const float*)d_in[18];
    const float* bf2 = (const float*)d_in[19];
    const float* g_ln = (const float*)d_in[20];
    const float* b_ln = (const float*)d_in[21];
    float* out = (float*)d_out;

    void *pden, *ph, *pq, *pk, *pv;
    cudaGetSymbolAddress(&pden, g_den);
    cudaGetSymbolAddress(&ph, g_h);
    cudaGetSymbolAddress(&pq, g_q);
    cudaGetSymbolAddress(&pk, g_k);
    cudaGetSymbolAddress(&pv, g_v);
    void *pwq, *pwk, *pwv;
    cudaGetSymbolAddress(&pwq, g_WtQ);
    cudaGetSymbolAddress(&pwk, g_WtK);
    cudaGetSymbolAddress(&pwv, g_WtV);

    const size_t LIN_SMEM = (size_t)(2 * 128 * PIT) * 4;                 // 135168
    const size_t EDGE_SMEM = (size_t)(128 * PIT + 256 * PIT + 256) * 4;  // 203776+1024
    const size_t FIN_SMEM = (size_t)(3 * 128 * PIT + 512) * 4;           // 204800
    cudaFuncSetAttribute(linear_tc, cudaFuncAttributeMaxDynamicSharedMemorySize, (int)LIN_SMEM);
    cudaFuncSetAttribute(edge_tc, cudaFuncAttributeMaxDynamicSharedMemorySize, (int)EDGE_SMEM);
    cudaFuncSetAttribute(final_tc, cudaFuncAttributeMaxDynamicSharedMemorySize, (int)FIN_SMEM);

    cudaMemsetAsync(pden, 0, (size_t)NN * 128 * sizeof(float), 0);
    cudaMemsetAsync(ph, 0, (size_t)NN * 128 * sizeof(float), 0);

    prep_T<<<128, 128>>>(Wq, Wk, Wv, We, Wm, Wf1, Wf2, g_f);
    prep_V<<<1, 128>>>(Wf2, b_f, g_f, bf2);

    linear_tc<<<148, 256, LIN_SMEM>>>(node_feats, (const uint32_t*)pwq, bq, (float*)pq, NN);
    linear_tc<<<148, 256, LIN_SMEM>>>(node_feats, (const uint32_t*)pwk, bk, (float*)pk, NN);
    linear_tc<<<148, 256, LIN_SMEM>>>(node_feats, (const uint32_t*)pwv, bv, (float*)pv, NN);

    edge_tc<<<148, 256, EDGE_SMEM>>>(edge_feats, be, bm, src, dst);

    final_tc<<<148, 256, FIN_SMEM>>>(node_feats, bf1, g_ln, b_ln, out);

    // edge_feats passthrough
    cudaMemcpyAsync(out + (size_t)NN * 128, edge_feats,
                    (size_t)NE * 128 * sizeof(float), cudaMemcpyDeviceToDevice, 0);
}

// round 4
// speedup vs baseline: 3.1815x; 1.1279x over previous
#include <cuda_runtime.h>
#include <cstdint>
#include <math.h>

#define NN 50000
#define NE 800000
#define PIT 132  // smem row pitch in 4B words: 132%32=4 -> conflict-free frag loads

// ----------------------------- scratch globals -----------------------------
__device__ float g_q[NN * 128];
__device__ float g_k[NN * 128];
__device__ float g_v[NN * 128];
__device__ float g_den[NN * 128];
__device__ float g_h[NN * 128];

// weights transposed to [n][k], tf32-rounded bit patterns
__device__ uint32_t g_WtQ[128 * 128];
__device__ uint32_t g_WtK[128 * 128];
__device__ uint32_t g_WtV[128 * 128];
__device__ uint32_t g_WtF1[128 * 128];
__device__ uint32_t g_WtF2g[128 * 128];
__device__ uint32_t g_WtEM[256 * 128];  // channel-permuted [We|Wm]
__device__ float g_vb[128];
__device__ float g_vg[128];

// ----------------------------- helpers -------------------------------------
__device__ __forceinline__ uint32_t rna(float x) {
    uint32_t r;
    asm("cvt.rna.tf32.f32 %0, %1;" : "=r"(r) : "f"(x));
    return r;
}

__device__ __forceinline__ void mma8(float* c, const uint32_t* a, const uint32_t* b) {
    asm volatile(
        "mma.sync.aligned.m16n8k8.row.col.f32.tf32.tf32.f32 "
        "{%0,%1,%2,%3}, {%4,%5,%6,%7}, {%8,%9}, {%0,%1,%2,%3};"
        : "+f"(c[0]), "+f"(c[1]), "+f"(c[2]), "+f"(c[3])
        : "r"(a[0]), "r"(a[1]), "r"(a[2]), "r"(a[3]), "r"(b[0]), "r"(b[1]));
}

__device__ __forceinline__ float mishf(float x) {
    float sp = (x > 20.f) ? x : log1pf(__expf(x));
    return x * tanhf(sp);
}

// ----------------------------- prep kernels --------------------------------
// EM column permutation: j in [0,256) -> (warp_n=j>>6, nt=(j>>3)&7, t=(j>>1)&3,
// par=j&1), channel = warp_n*32 + t*8 + nt. Gives each MMA thread 8 consecutive
// channels with (e,m) adjacent in its accumulator fragment.
__global__ void prep_T(const float* __restrict__ Wq, const float* __restrict__ Wk,
                       const float* __restrict__ Wv, const float* __restrict__ We,
                       const float* __restrict__ Wm, const float* __restrict__ Wf1,
                       const float* __restrict__ Wf2, const float* __restrict__ gf) {
    int k = blockIdx.x, n = threadIdx.x;
    int s = k * 128 + n, d = n * 128 + k;
    g_WtQ[d] = rna(Wq[s]);
    g_WtK[d] = rna(Wk[s]);
    g_WtV[d] = rna(Wv[s]);
    g_WtF1[d] = rna(Wf1[s]);
    g_WtF2g[d] = rna(gf[k] * Wf2[s]);
#pragma unroll
    for (int jj = 0; jj < 2; jj++) {
        int j = n + jj * 128;
        int wn = j >> 6, wi = j & 63, nt = wi >> 3, rem = wi & 7, tt = rem >> 1, par = rem & 1;
        int ch = wn * 32 + tt * 8 + nt;
        const float* W = par ? Wm : We;
        g_WtEM[j * 128 + k] = rna(W[k * 128 + ch]);
    }
}

__global__ void prep_V(const float* __restrict__ Wf2, const float* __restrict__ bf,
                       const float* __restrict__ gf, const float* __restrict__ bf2) {
    int n = threadIdx.x;
    float a = 0.f, b = 0.f;
    for (int k = 0; k < 128; k++) {
        float w = Wf2[k * 128 + n];
        a = fmaf(bf[k], w, a);
        b = fmaf(gf[k], w, b);
    }
    g_vb[n] = bf2[n] + a;
    g_vg[n] = b;
}

// ----------------------------- linear: Y = X@W + b -------------------------
// 512 thr = 16 warps (4 m x 4 n), warp tile m32 x n32, tf32 mma.sync.
__global__ __launch_bounds__(512, 1) void linear_tc(
    const float* __restrict__ X, const uint32_t* __restrict__ Bt,
    const float* __restrict__ bias, float* __restrict__ Y, int M) {
    extern __shared__ __align__(16) uint32_t sm[];
    uint32_t* sA = sm;            // 128*PIT
    uint32_t* sB = sm + 128 * PIT;

    int tid = threadIdx.x, w = tid >> 5, lane = tid & 31;
    int wm = w >> 2, wn = w & 3, g = lane >> 2, t = lane & 3;

    for (int i = tid; i < 128 * 32; i += 512) {
        int r = i >> 5, c = (i & 31) * 4;
        *(uint4*)(sB + r * PIT + c) = *(const uint4*)(Bt + r * 128 + c);
    }
    float bc[4][2];
#pragma unroll
    for (int nt = 0; nt < 4; nt++) {
        int col = wn * 32 + nt * 8 + t * 2;
        bc[nt][0] = __ldg(bias + col);
        bc[nt][1] = __ldg(bias + col + 1);
    }

    int nT = (M + 127) >> 7;
    for (int tt = blockIdx.x; tt < nT; tt += gridDim.x) {
        __syncthreads();
        int base = tt << 7;
        for (int i = tid; i < 128 * 32; i += 512) {
            int r = i >> 5, c = (i & 31) * 4;
            int row = base + r;
            uint4 u = make_uint4(0u, 0u, 0u, 0u);
            if (row < M) {
                float4 x = *(const float4*)(X + (size_t)row * 128 + c);
                u.x = rna(x.x); u.y = rna(x.y); u.z = rna(x.z); u.w = rna(x.w);
            }
            *(uint4*)(sA + r * PIT + c) = u;
        }
        __syncthreads();

        float c_[2][4][4];
#pragma unroll
        for (int mt = 0; mt < 2; mt++)
#pragma unroll
            for (int nt = 0; nt < 4; nt++)
#pragma unroll
                for (int i = 0; i < 4; i++) c_[mt][nt][i] = 0.f;

#pragma unroll
        for (int k0 = 0; k0 < 128; k0 += 8) {
            uint32_t a[2][4], b[4][2];
#pragma unroll
            for (int mt = 0; mt < 2; mt++) {
                int r = wm * 32 + mt * 16 + g;
                a[mt][0] = sA[r * PIT + k0 + t];
                a[mt][1] = sA[(r + 8) * PIT + k0 + t];
                a[mt][2] = sA[r * PIT + k0 + t + 4];
                a[mt][3] = sA[(r + 8) * PIT + k0 + t + 4];
            }
#pragma unroll
            for (int nt = 0; nt < 4; nt++) {
                int n = wn * 32 + nt * 8 + g;
                b[nt][0] = sB[n * PIT + k0 + t];
                b[nt][1] = sB[n * PIT + k0 + t + 4];
            }
#pragma unroll
            for (int mt = 0; mt < 2; mt++)
#pragma unroll
                for (int nt = 0; nt < 4; nt++) mma8(c_[mt][nt], a[mt], b[nt]);
        }

#pragma unroll
        for (int mt = 0; mt < 2; mt++) {
            int row = base + wm * 32 + mt * 16 + g;
#pragma unroll
            for (int nt = 0; nt < 4; nt++) {
                int col = wn * 32 + nt * 8 + t * 2;
                if (row < M) {
                    float2 o = make_float2(c_[mt][nt][0] + bc[nt][0], c_[mt][nt][1] + bc[nt][1]);
                    *(float2*)(Y + (size_t)row * 128 + col) = o;
                }
                if (row + 8 < M) {
                    float2 o = make_float2(c_[mt][nt][2] + bc[nt][0], c_[mt][nt][3] + bc[nt][1]);
                    *(float2*)(Y + (size_t)(row + 8) * 128 + col) = o;
                }
            }
        }
    }
}

// ----------------------------- fused edge pass ------------------------------
// [e|m](perm) = EF @ WtEM ; p = exp((m+bm)*(q[src]-k[dst]) + e+be)
// den[dst] += p ; h[dst] += p*v[src]  (float4 atomics).
// Also streams raw EF bytes to outE (fused passthrough copy).
// 512 thr = 16 warps (4 m x 4 n), warp tile m32 x n64 over N=256.
__global__ __launch_bounds__(512, 1) void edge_tc(
    const float* __restrict__ EF, const float* __restrict__ be,
    const float* __restrict__ bm, const int* __restrict__ src,
    const int* __restrict__ dst, float* __restrict__ outE) {
    extern __shared__ __align__(16) uint32_t sm[];
    uint32_t* sA = sm;                 // 128*PIT
    uint32_t* sB = sm + 128 * PIT;     // 256*PIT
    int* ssrc = (int*)(sm + 128 * PIT + 256 * PIT);
    int* sdst = ssrc + 128;

    int tid = threadIdx.x, w = tid >> 5, lane = tid & 31;
    int wm = w >> 2, wn = w & 3, g = lane >> 2, t = lane & 3;
    int chb = wn * 32 + t * 8;

    for (int i = tid; i < 256 * 32; i += 512) {
        int r = i >> 5, c = (i & 31) * 4;
        *(uint4*)(sB + r * PIT + c) = *(const uint4*)(g_WtEM + r * 128 + c);
    }
    float bea[8], bma[8];
    *(float4*)(bea) = __ldg((const float4*)(be + chb));
    *(float4*)(bea + 4) = __ldg((const float4*)(be + chb + 4));
    *(float4*)(bma) = __ldg((const float4*)(bm + chb));
    *(float4*)(bma + 4) = __ldg((const float4*)(bm + chb + 4));

    const int nT = NE / 128;  // 6250 exact
    for (int tt = blockIdx.x; tt < nT; tt += gridDim.x) {
        __syncthreads();
        int base = tt << 7;
        if (tid < 128) {
            ssrc[tid] = src[base + tid];
            sdst[tid] = dst[base + tid];
        }
        for (int i = tid; i < 128 * 32; i += 512) {
            int r = i >> 5, c = (i & 31) * 4;
            float4 x = *(const float4*)(EF + (size_t)(base + r) * 128 + c);
            // fused passthrough: raw bytes to output
            *(float4*)(outE + (size_t)(base + r) * 128 + c) = x;
            uint4 u;
            u.x = rna(x.x); u.y = rna(x.y); u.z = rna(x.z); u.w = rna(x.w);
            *(uint4*)(sA + r * PIT + c) = u;
        }
        __syncthreads();

        float c_[2][8][4];
#pragma unroll
        for (int mt = 0; mt < 2; mt++)
#pragma unroll
            for (int nt = 0; nt < 8; nt++)
#pragma unroll
                for (int i = 0; i < 4; i++) c_[mt][nt][i] = 0.f;

#pragma unroll
        for (int k0 = 0; k0 < 128; k0 += 8) {
            uint32_t a[2][4], b[8][2];
#pragma unroll
            for (int mt = 0; mt < 2; mt++) {
                int r = wm * 32 + mt * 16 + g;
                a[mt][0] = sA[r * PIT + k0 + t];
                a[mt][1] = sA[(r + 8) * PIT + k0 + t];
                a[mt][2] = sA[r * PIT + k0 + t + 4];
                a[mt][3] = sA[(r + 8) * PIT + k0 + t + 4];
            }
#pragma unroll
            for (int nt = 0; nt < 8; nt++) {
                int n = wn * 64 + nt * 8 + g;
                b[nt][0] = sB[n * PIT + k0 + t];
                b[nt][1] = sB[n * PIT + k0 + t + 4];
            }
#pragma unroll
            for (int mt = 0; mt < 2; mt++)
#pragma unroll
                for (int nt = 0; nt < 8; nt++) mma8(c_[mt][nt], a[mt], b[nt]);
        }

        // epilogue: thread owns channels [chb, chb+8) for rows (mt, g/g+8)
#pragma unroll
        for (int mt = 0; mt < 2; mt++) {
#pragma unroll
            for (int rs = 0; rs < 2; rs++) {
                int rl = wm * 32 + mt * 16 + g + rs * 8;
                int s = ssrc[rl], d = sdst[rl];
                float qa[8], ka[8], va[8];
                const float4* qp = (const float4*)(g_q + (size_t)s * 128 + chb);
                const float4* kp = (const float4*)(g_k + (size_t)d * 128 + chb);
                const float4* vp = (const float4*)(g_v + (size_t)s * 128 + chb);
                *(float4*)(qa) = __ldg(qp);     *(float4*)(qa + 4) = __ldg(qp + 1);
                *(float4*)(ka) = __ldg(kp);     *(float4*)(ka + 4) = __ldg(kp + 1);
                *(float4*)(va) = __ldg(vp);     *(float4*)(va + 4) = __ldg(vp + 1);
                float p[8], pv[8];
#pragma unroll
                for (int nt = 0; nt < 8; nt++) {
                    float ev = c_[mt][nt][rs * 2] + bea[nt];
                    float mv = c_[mt][nt][rs * 2 + 1] + bma[nt];
                    p[nt] = __expf(fmaf(mv, qa[nt] - ka[nt], ev));
                    pv[nt] = p[nt] * va[nt];
                }
                float4* dp = (float4*)(g_den + (size_t)d * 128 + chb);
                float4* hp = (float4*)(g_h + (size_t)d * 128 + chb);
                atomicAdd(dp, make_float4(p[0], p[1], p[2], p[3]));
                atomicAdd(dp + 1, make_float4(p[4], p[5], p[6], p[7]));
                atomicAdd(hp, make_float4(pv[0], pv[1], pv[2], pv[3]));
                atomicAdd(hp + 1, make_float4(pv[4], pv[5], pv[6], pv[7]));
            }
        }
    }
}

// ----------------------------- final fused MLP ------------------------------
// x = h/den + NF ; u = mish(x@Wf1+bf1) ; LN1 folded through GEMM2:
// y = inv1*(u@(g_f.*Wf2)) + vb - mu1*inv1*vg ; out = LN2(y)*g_ln + b_ln
__global__ __launch_bounds__(256, 1) void final_tc(
    const float* __restrict__ NF, const float* __restrict__ bf1,
    const float* __restrict__ gln, const float* __restrict__ bln,
    float* __restrict__ out) {
    extern __shared__ __align__(16) uint32_t sm[];
    uint32_t* sA = sm;
    uint32_t* sB1 = sm + 128 * PIT;
    uint32_t* sB2 = sm + 2 * 128 * PIT;
    float* smu = (float*)(sm + 3 * 128 * PIT);
    float* sinv = smu + 128;
    float* sgl = sinv + 128;
    float* sbl = sgl + 128;

    int tid = threadIdx.x, w = tid >> 5, lane = tid & 31;
    int wm = w >> 2, wn = w & 3, g = lane >> 2, t = lane & 3;

    for (int i = tid; i < 128 * 32; i += 256) {
        int r = i >> 5, c = (i & 31) * 4;
        *(uint4*)(sB1 + r * PIT + c) = *(const uint4*)(g_WtF1 + r * 128 + c);
        *(uint4*)(sB2 + r * PIT + c) = *(const uint4*)(g_WtF2g + r * 128 + c);
    }
    if (tid < 128) {
        sgl[tid] = gln[tid];
        sbl[tid] = bln[tid];
    }
    float b1c[4][2], vbc[4][2], vgc[4][2];
#pragma unroll
    for (int nt = 0; nt < 4; nt++) {
        int col = wn * 32 + nt * 8 + t * 2;
        b1c[nt][0] = __ldg(bf1 + col);   b1c[nt][1] = __ldg(bf1 + col + 1);
        vbc[nt][0] = g_vb[col];          vbc[nt][1] = g_vb[col + 1];
        vgc[nt][0] = g_vg[col];          vgc[nt][1] = g_vg[col + 1];
    }

    int srow = tid >> 1, shalf = tid & 1;
    const int nT = (NN + 127) >> 7;
    for (int tt = blockIdx.x; tt < nT; tt += gridDim.x) {
        __syncthreads();
        int base = tt << 7;
        for (int i = tid; i < 128 * 32; i += 256) {
            int r = i >> 5, c = (i & 31) * 4;
            int row = base + r;
            uint4 u = make_uint4(0u, 0u, 0u, 0u);
            if (row < NN) {
                float4 hh = *(const float4*)(g_h + (size_t)row * 128 + c);
                float4 dn = *(const float4*)(g_den + (size_t)row * 128 + c);
                float4 nf = *(const float4*)(NF + (size_t)row * 128 + c);
                u.x = rna((dn.x > 0.f ? hh.x / dn.x : 0.f) + nf.x);
                u.y = rna((dn.y > 0.f ? hh.y / dn.y : 0.f) + nf.y);
                u.z = rna((dn.z > 0.f ? hh.z / dn.z : 0.f) + nf.z);
                u.w = rna((dn.w > 0.f ? hh.w / dn.w : 0.f) + nf.w);
            }
            *(uint4*)(sA + r * PIT + c) = u;
        }
        __syncthreads();

        // GEMM1: u = x @ Wf1
        float c_[4][4][4];
#pragma unroll
        for (int mt = 0; mt < 4; mt++)
#pragma unroll
            for (int nt = 0; nt < 4; nt++)
#pragma unroll
                for (int i = 0; i < 4; i++) c_[mt][nt][i] = 0.f;
#pragma unroll
        for (int k0 = 0; k0 < 128; k0 += 8) {
            uint32_t a[4][4], b[4][2];
#pragma unroll
            for (int mt = 0; mt < 4; mt++) {
                int r = wm * 64 + mt * 16 + g;
                a[mt][0] = sA[r * PIT + k0 + t];
                a[mt][1] = sA[(r + 8) * PIT + k0 + t];
                a[mt][2] = sA[r * PIT + k0 + t + 4];
                a[mt][3] = sA[(r + 8) * PIT + k0 + t + 4];
            }
#pragma unroll
            for (int nt = 0; nt < 4; nt++) {
                int n = wn * 32 + nt * 8 + g;
                b[nt][0] = sB1[n * PIT + k0 + t];
                b[nt][1] = sB1[n * PIT + k0 + t + 4];
            }
#pragma unroll
            for (int mt = 0; mt < 4; mt++)
#pragma unroll
                for (int nt = 0; nt < 4; nt++) mma8(c_[mt][nt], a[mt], b[nt]);
        }
        __syncthreads();  // all reads of sA(x) done

        // mish, write u (tf32) back to sA
#pragma unroll
        for (int mt = 0; mt < 4; mt++) {
            int r0 = wm * 64 + mt * 16 + g;
#pragma unroll
            for (int nt = 0; nt < 4; nt++) {
                int col = wn * 32 + nt * 8 + t * 2;
                uint2 u0, u1;
                u0.x = rna(mishf(c_[mt][nt][0] + b1c[nt][0]));
                u0.y = rna(mishf(c_[mt][nt][1] + b1c[nt][1]));
                u1.x = rna(mishf(c_[mt][nt][2] + b1c[nt][0]));
                u1.y = rna(mishf(c_[mt][nt][3] + b1c[nt][1]));
                *(uint2*)(sA + r0 * PIT + col) = u0;
                *(uint2*)(sA + (r0 + 8) * PIT + col) = u1;
            }
        }
        __syncthreads();

        // LN1 row stats (2 threads per row)
        {
            float s1 = 0.f, s2 = 0.f;
            const uint32_t* rp = sA + srow * PIT + shalf * 64;
#pragma unroll
            for (int i = 0; i < 16; i++) {
                uint4 uu = *(const uint4*)(rp + i * 4);
                float x0 = __uint_as_float(uu.x), x1 = __uint_as_float(uu.y);
                float x2 = __uint_as_float(uu.z), x3 = __uint_as_float(uu.w);
                s1 += x0 + x1 + x2 + x3;
                s2 += x0 * x0 + x1 * x1 + x2 * x2 + x3 * x3;
            }
            s1 += __shfl_xor_sync(0xffffffffu, s1, 1);
            s2 += __shfl_xor_sync(0xffffffffu, s2, 1);
            if (shalf == 0) {
                float mu = s1 * (1.f / 128.f);
                smu[srow] = mu;
                sinv[srow] = rsqrtf(s2 * (1.f / 128.f) - mu * mu + 1e-5f);
            }
        }
        __syncthreads();

        // GEMM2: acc = u @ (g_f .* Wf2)
        float c2[4][4][4];
#pragma unroll
        for (int mt = 0; mt < 4; mt++)
#pragma unroll
            for (int nt = 0; nt < 4; nt++)
#pragma unroll
                for (int i = 0; i < 4; i++) c2[mt][nt][i] = 0.f;
#pragma unroll
        for (int k0 = 0; k0 < 128; k0 += 8) {
            uint32_t a[4][4], b[4][2];
#pragma unroll
            for (int mt = 0; mt < 4; mt++) {
                int r = wm * 64 + mt * 16 + g;
                a[mt][0] = sA[r * PIT + k0 + t];
                a[mt][1] = sA[(r + 8) * PIT + k0 + t];
                a[mt][2] = sA[r * PIT + k0 + t + 4];
                a[mt][3] = sA[(r + 8) * PIT + k0 + t + 4];
            }
#pragma unroll
            for (int nt = 0; nt < 4; nt++) {
                int n = wn * 32 + nt * 8 + g;
                b[nt][0] = sB2[n * PIT + k0 + t];
                b[nt][1] = sB2[n * PIT + k0 + t + 4];
            }
#pragma unroll
            for (int mt = 0; mt < 4; mt++)
#pragma unroll
                for (int nt = 0; nt < 4; nt++) mma8(c2[mt][nt], a[mt], b[nt]);
        }
        __syncthreads();  // all reads of sA(u) done

        // y = inv1*acc + vb - mu1*inv1*vg, write y (f32 bits) to sA
#pragma unroll
        for (int mt = 0; mt < 4; mt++) {
            int r0 = wm * 64 + mt * 16 + g;
            float mu0 = smu[r0], iv0 = sinv[r0];
            float mu8 = smu[r0 + 8], iv8 = sinv[r0 + 8];
#pragma unroll
            for (int nt = 0; nt < 4; nt++) {
                int col = wn * 32 + nt * 8 + t * 2;
                uint2 y0, y1;
                y0.x = __float_as_uint(iv0 * c2[mt][nt][0] + vbc[nt][0] - mu0 * iv0 * vgc[nt][0]);
                y0.y = __float_as_uint(iv0 * c2[mt][nt][1] + vbc[nt][1] - mu0 * iv0 * vgc[nt][1]);
                y1.x = __float_as_uint(iv8 * c2[mt][nt][2] + vbc[nt][0] - mu8 * iv8 * vgc[nt][0]);
                y1.y = __float_as_uint(iv8 * c2[mt][nt][3] + vbc[nt][1] - mu8 * iv8 * vgc[nt][1]);
                *(uint2*)(sA + r0 * PIT + col) = y0;
                *(uint2*)(sA + (r0 + 8) * PIT + col) = y1;
            }
        }
        __syncthreads();

        // LN2 row stats
        {
            float s1 = 0.f, s2 = 0.f;
            const uint32_t* rp = sA + srow * PIT + shalf * 64;
#pragma unroll
            for (int i = 0; i < 16; i++) {
                uint4 uu = *(const uint4*)(rp + i * 4);
                float x0 = __uint_as_float(uu.x), x1 = __uint_as_float(uu.y);
                float x2 = __uint_as_float(uu.z), x3 = __uint_as_float(uu.w);
                s1 += x0 + x1 + x2 + x3;
                s2 += x0 * x0 + x1 * x1 + x2 * x2 + x3 * x3;
            }
            s1 += __shfl_xor_sync(0xffffffffu, s1, 1);
            s2 += __shfl_xor_sync(0xffffffffu, s2, 1);
            if (shalf == 0) {
                float mu = s1 * (1.f / 128.f);
                smu[srow] = mu;
                sinv[srow] = rsqrtf(s2 * (1.f / 128.f) - mu * mu + 1e-5f);
            }
        }
        __syncthreads();

        // final store
        {
            int row = base + srow;
            if (row < NN) {
                float mu = smu[srow], iv = sinv[srow];
                const uint32_t* rp = sA + srow * PIT + shalf * 64;
#pragma unroll
                for (int i = 0; i < 16; i++) {
                    int col = shalf * 64 + i * 4;
                    uint4 uu = *(const uint4*)(rp + i * 4);
                    float4 o;
                    o.x = (__uint_as_float(uu.x) - mu) * iv * sgl[col + 0] + sbl[col + 0];
                    o.y = (__uint_as_float(uu.y) - mu) * iv * sgl[col + 1] + sbl[col + 1];
                    o.z = (__uint_as_float(uu.z) - mu) * iv * sgl[col + 2] + sbl[col + 2];
                    o.w = (__uint_as_float(uu.w) - mu) * iv * sgl[col + 3] + sbl[col + 3];
                    *(float4*)(out + (size_t)row * 128 + col) = o;
                }
            }
        }
    }
}

// ---------------------------------------------------------------------------
extern "C" void kernel_launch(void* const* d_in, const int* in_sizes, int n_in,
                              void* d_out, int out_size) {
    const float* node_feats = (const float*)d_in[0];
    const float* edge_feats = (const float*)d_in[1];
    const int* src = (const int*)d_in[2];
    const int* dst = (const int*)d_in[3];
    const float* Wq = (const float*)d_in[4];
    const float* bq = (const float*)d_in[5];
    const float* Wk = (const float*)d_in[6];
    const float* bk = (const float*)d_in[7];
    const float* Wv = (const float*)d_in[8];
    const float* bv = (const float*)d_in[9];
    const float* We = (const float*)d_in[10];
    const float* be = (const float*)d_in[11];
    const float* Wm = (const float*)d_in[12];
    const float* bm = (const float*)d_in[13];
    const float* Wf1 = (const float*)d_in[14];
    const float* bf1 = (const float*)d_in[15];
    const float* g_f = (const float*)d_in[16];
    const float* b_f = (const float*)d_in[17];
    const float* Wf2 = (const float*)d_in[18];
    const float* bf2 = (const float*)d_in[19];
    const float* g_ln = (const float*)d_in[20];
    const float* b_ln = (const float*)d_in[21];
    float* out = (float*)d_out;

    void *pden, *ph, *pq, *pk, *pv;
    cudaGetSymbolAddress(&pden, g_den);
    cudaGetSymbolAddress(&ph, g_h);
    cudaGetSymbolAddress(&pq, g_q);
    cudaGetSymbolAddress(&pk, g_k);
    cudaGetSymbolAddress(&pv, g_v);
    void *pwq, *pwk, *pwv;
    cudaGetSymbolAddress(&pwq, g_WtQ);
    cudaGetSymbolAddress(&pwk, g_WtK);
    cudaGetSymbolAddress(&pwv, g_WtV);

    const size_t LIN_SMEM = (size_t)(2 * 128 * PIT) * 4;                 // 135168
    const size_t EDGE_SMEM = (size_t)(128 * PIT + 256 * PIT + 256) * 4;  // 203776+1024
    const size_t FIN_SMEM = (size_t)(3 * 128 * PIT + 512) * 4;           // 204800
    cudaFuncSetAttribute(linear_tc, cudaFuncAttributeMaxDynamicSharedMemorySize, (int)LIN_SMEM);
    cudaFuncSetAttribute(edge_tc, cudaFuncAttributeMaxDynamicSharedMemorySize, (int)EDGE_SMEM);
    cudaFuncSetAttribute(final_tc, cudaFuncAttributeMaxDynamicSharedMemorySize, (int)FIN_SMEM);

    cudaMemsetAsync(pden, 0, (size_t)NN * 128 * sizeof(float), 0);
    cudaMemsetAsync(ph, 0, (size_t)NN * 128 * sizeof(float), 0);

    prep_T<<<128, 128>>>(Wq, Wk, Wv, We, Wm, Wf1, Wf2, g_f);
    prep_V<<<1, 128>>>(Wf2, b_f, g_f, bf2);

    linear_tc<<<148, 512, LIN_SMEM>>>(node_feats, (const uint32_t*)pwq, bq, (float*)pq, NN);
    linear_tc<<<148, 512, LIN_SMEM>>>(node_feats, (const uint32_t*)pwk, bk, (float*)pk, NN);
    linear_tc<<<148, 512, LIN_SMEM>>>(node_feats, (const uint32_t*)pwv, bv, (float*)pv, NN);

    // edge pass also streams the edge_feats passthrough to out
    edge_tc<<<148, 512, EDGE_SMEM>>>(edge_feats, be, bm, src, dst, out + (size_t)NN * 128);

    final_tc<<<148, 256, FIN_SMEM>>>(node_feats, bf1, g_ln, b_ln, out);
}